// round 2
// baseline (speedup 1.0000x reference)
#include <cuda_runtime.h>
#include <mma.h>
#include <cstdint>

using namespace nvcuda;

#define CC      256
#define HH      384
#define WW      384
#define NHEADS  8
#define HD      32
#define THREADS 128
#define LDA     264   // q_in / kv_in row stride (floats), pad to kill bank conflicts
#define LDW     40    // per-head weight stage + Qh/Kh/Vh/O stride
#define LDSC    24    // score tile stride

// SMEM layout (floats)
#define OFF_Q   0          // 64*264 = 16896
#define OFF_KV  16896      // 16896
#define OFF_W   33792      // weight stage: max(256*40, 32*264) = 10240
#define OFF_QH  44032      // 4 * 16*40 = 2560
#define OFF_KH  46592
#define OFF_VH  49152
#define OFF_S   51712      // 4 * 16*24 = 1536
#define OFF_B   53248      // 256 (bias[16][16])
#define SMEM_FLOATS 53504
#define SMEM_BYTES  (SMEM_FLOATS * 4)

template <class Frag>
static __device__ __forceinline__ void to_tf32(Frag& f) {
#pragma unroll
    for (int i = 0; i < f.num_elements; i++) f.x[i] = wmma::__float_to_tf32(f.x[i]);
}

// Stage a [rows x 32] fp32 weight column-block into sW (ld = LDW)
static __device__ __forceinline__ void stageW(float* dst, const float* __restrict__ src,
                                              int rows, int srcld) {
    for (int i = threadIdx.x; i < rows * 8; i += THREADS) {
        int r = i >> 3, j = (i & 7) * 4;
        float4 v = *(const float4*)(src + (size_t)r * srcld + j);
        *(float4*)(dst + r * LDW + j) = v;
    }
}

// Stage wo rows [32 x 256] into sW (ld = 264)
static __device__ __forceinline__ void stageWo(float* dst, const float* __restrict__ src) {
    for (int i = threadIdx.x; i < 32 * 64; i += THREADS) {
        int r = i >> 6, j = (i & 63) * 4;
        float4 v = *(const float4*)(src + r * 256 + j);
        *(float4*)(dst + r * 264 + j) = v;
    }
}

// Per-warp: [16,32] = sIn(16 rows, 256 cols, ld LDA) @ sW(256x32, ld LDW) + bias
static __device__ __forceinline__ void proj16x32(const float* sIn, const float* sW,
                                                 float* sOut, const float* __restrict__ bias_g) {
    wmma::fragment<wmma::accumulator, 16, 16, 8, float> c0, c1;
    wmma::fill_fragment(c0, 0.0f);
    wmma::fill_fragment(c1, 0.0f);
#pragma unroll 8
    for (int kk = 0; kk < 32; kk++) {
        wmma::fragment<wmma::matrix_a, 16, 16, 8, wmma::precision::tf32, wmma::row_major> a;
        wmma::load_matrix_sync(a, sIn + kk * 8, LDA);
        to_tf32(a);
        wmma::fragment<wmma::matrix_b, 16, 16, 8, wmma::precision::tf32, wmma::row_major> b0, b1;
        wmma::load_matrix_sync(b0, sW + kk * 8 * LDW, LDW);
        to_tf32(b0);
        wmma::load_matrix_sync(b1, sW + kk * 8 * LDW + 16, LDW);
        to_tf32(b1);
        wmma::mma_sync(c0, a, b0, c0);
        wmma::mma_sync(c1, a, b1, c1);
    }
    wmma::store_matrix_sync(sOut, c0, LDW, wmma::mem_row_major);
    wmma::store_matrix_sync(sOut + 16, c1, LDW, wmma::mem_row_major);
    __syncwarp();
    int lane = threadIdx.x & 31;
    float bv = __ldg(bias_g + lane);
#pragma unroll
    for (int r = 0; r < 16; r++) sOut[r * LDW + lane] += bv;
    __syncwarp();
}

__global__ void __launch_bounds__(THREADS, 1)
xattn_kernel(const float* __restrict__ x, const float* __restrict__ cond,
             const float* __restrict__ n1w, const float* __restrict__ n2w,
             const float* __restrict__ wq, const float* __restrict__ bq,
             const float* __restrict__ wkv, const float* __restrict__ bkv,
             const float* __restrict__ wo, const float* __restrict__ bo,
             const float* __restrict__ btab, float* __restrict__ out)
{
    extern __shared__ float sm[];
    float* sQ  = sm + OFF_Q;
    float* sKV = sm + OFF_KV;
    float* sW  = sm + OFF_W;
    float* sQH = sm + OFF_QH;
    float* sKH = sm + OFF_KH;
    float* sVH = sm + OFF_VH;
    float* sS  = sm + OFF_S;
    float* sB  = sm + OFF_B;

    const int tid = threadIdx.x, lane = tid & 31, warp = tid >> 5;
    const int wc = blockIdx.x, hr = blockIdx.y, b = blockIdx.z;
    const int h0 = hr * 4, w0 = wc * 16;

    // ---- Load x -> sKV, cond -> sQ (token-major), fully-coalesced 64B rows ----
    for (int i = tid; i < CC * 16; i += THREADS) {
        int c = i >> 4, rw = i & 15, r = rw >> 2, w4 = rw & 3;
        size_t off = ((size_t)(b * CC + c) * HH + (h0 + r)) * WW + w0 + w4 * 4;
        float4 vx = *(const float4*)(x + off);
        float4 vc = *(const float4*)(cond + off);
        int t0 = w4 * 16 + r * 4;  // window = w4, rows of tokens t0..t0+3
        float* kvc = sKV + c;
        float* qc  = sQ + c;
        kvc[(t0 + 0) * LDA] = vx.x; kvc[(t0 + 1) * LDA] = vx.y;
        kvc[(t0 + 2) * LDA] = vx.z; kvc[(t0 + 3) * LDA] = vx.w;
        qc[(t0 + 0) * LDA] = vc.x;  qc[(t0 + 1) * LDA] = vc.y;
        qc[(t0 + 2) * LDA] = vc.z;  qc[(t0 + 3) * LDA] = vc.w;
    }
    // ---- Relative-position bias table (16x16) ----
    for (int i = tid; i < 256; i += THREADS) {
        int n = i >> 4, m = i & 15;
        int dr = (n >> 2) - (m >> 2) + 3;
        int dc = (n & 3) - (m & 3) + 3;
        sB[i] = __ldg(btab + dr * 7 + dc);
    }
    __syncthreads();

    // ---- LayerNorm: 128 tasks = {sQ,sKV} x 64 tokens ----
    {
        int tk = tid & 63;
        float* row = (tid < 64 ? sQ : sKV) + tk * LDA;
        const float* nw = (tid < 64) ? n1w : n2w;
        float s = 0.f, s2 = 0.f;
#pragma unroll 8
        for (int c = 0; c < CC; c++) { float v = row[c]; s += v; s2 += v * v; }
        float mean = s * (1.0f / CC);
        float var  = s2 * (1.0f / CC) - mean * mean;
        float rstd = rsqrtf(var + 1e-5f);
#pragma unroll 8
        for (int c = 0; c < CC; c++) row[c] = (row[c] - mean) * rstd * __ldg(nw + c);
    }

    // ---- Output accumulator: [16 tokens, 256 ch] as 16 accum fragments ----
    wmma::fragment<wmma::accumulator, 16, 16, 8, float> acc[16];
#pragma unroll
    for (int j = 0; j < 16; j++) wmma::fill_fragment(acc[j], 0.0f);

    const float* sInQ  = sQ + warp * 16 * LDA;
    const float* sInKV = sKV + warp * 16 * LDA;
    float* myQH = sQH + warp * 640;
    float* myKH = sKH + warp * 640;
    float* myVH = sVH + warp * 640;
    float* myS  = sS + warp * 384;

    for (int h = 0; h < NHEADS; h++) {
        // Q projection
        __syncthreads();
        stageW(sW, wq + h * HD, CC, CC);
        __syncthreads();
        proj16x32(sInQ, sW, myQH, bq + h * HD);
        // K projection
        __syncthreads();
        stageW(sW, wkv + h * HD, CC, 2 * CC);
        __syncthreads();
        proj16x32(sInKV, sW, myKH, bkv + h * HD);
        // V projection
        __syncthreads();
        stageW(sW, wkv + CC + h * HD, CC, 2 * CC);
        __syncthreads();
        proj16x32(sInKV, sW, myVH, bkv + CC + h * HD);

        // scores = Qh @ Kh^T   (Kh row-major [16,32] == K^T col-major [32,16])
        {
            wmma::fragment<wmma::accumulator, 16, 16, 8, float> sc;
            wmma::fill_fragment(sc, 0.0f);
#pragma unroll
            for (int kk = 0; kk < 4; kk++) {
                wmma::fragment<wmma::matrix_a, 16, 16, 8, wmma::precision::tf32, wmma::row_major> a;
                wmma::load_matrix_sync(a, myQH + kk * 8, LDW);
                to_tf32(a);
                wmma::fragment<wmma::matrix_b, 16, 16, 8, wmma::precision::tf32, wmma::col_major> bK;
                wmma::load_matrix_sync(bK, myKH + kk * 8, LDW);
                to_tf32(bK);
                wmma::mma_sync(sc, a, bK, sc);
            }
            wmma::store_matrix_sync(myS, sc, LDSC, wmma::mem_row_major);
        }
        __syncwarp();
        // softmax (scale + bias, per row), lanes 0..15 each own one row
        if (lane < 16) {
            float* srow = myS + lane * LDSC;
            const float* brow = sB + lane * 16;
            float mx = -1e30f;
#pragma unroll
            for (int m = 0; m < 16; m++) {
                float v = srow[m] * 0.17677669529663687f + brow[m];
                srow[m] = v;
                mx = fmaxf(mx, v);
            }
            float sum = 0.f;
#pragma unroll
            for (int m = 0; m < 16; m++) { float e = __expf(srow[m] - mx); srow[m] = e; sum += e; }
            float inv = 1.0f / sum;
#pragma unroll
            for (int m = 0; m < 16; m++) srow[m] *= inv;
        }
        __syncwarp();
        // O_h = P @ Vh  -> reuse myQH
        {
            wmma::fragment<wmma::accumulator, 16, 16, 8, float> o0, o1;
            wmma::fill_fragment(o0, 0.0f);
            wmma::fill_fragment(o1, 0.0f);
#pragma unroll
            for (int kk = 0; kk < 2; kk++) {
                wmma::fragment<wmma::matrix_a, 16, 16, 8, wmma::precision::tf32, wmma::row_major> a;
                wmma::load_matrix_sync(a, myS + kk * 8, LDSC);
                to_tf32(a);
                wmma::fragment<wmma::matrix_b, 16, 16, 8, wmma::precision::tf32, wmma::row_major> b0, b1;
                wmma::load_matrix_sync(b0, myVH + kk * 8 * LDW, LDW);
                to_tf32(b0);
                wmma::load_matrix_sync(b1, myVH + kk * 8 * LDW + 16, LDW);
                to_tf32(b1);
                wmma::mma_sync(o0, a, b0, o0);
                wmma::mma_sync(o1, a, b1, o1);
            }
            wmma::store_matrix_sync(myQH, o0, LDW, wmma::mem_row_major);
            wmma::store_matrix_sync(myQH + 16, o1, LDW, wmma::mem_row_major);
        }
        // acc += O_h @ wo[h*32 : h*32+32, :]
        __syncthreads();
        stageWo(sW, wo + (size_t)h * HD * CC);
        __syncthreads();
        wmma::fragment<wmma::matrix_a, 16, 16, 8, wmma::precision::tf32, wmma::row_major> aO[4];
#pragma unroll
        for (int kk = 0; kk < 4; kk++) {
            wmma::load_matrix_sync(aO[kk], myQH + kk * 8, LDW);
            to_tf32(aO[kk]);
        }
#pragma unroll
        for (int j = 0; j < 16; j++) {
#pragma unroll
            for (int kk = 0; kk < 4; kk++) {
                wmma::fragment<wmma::matrix_b, 16, 16, 8, wmma::precision::tf32, wmma::row_major> bW;
                wmma::load_matrix_sync(bW, sW + kk * 8 * 264 + j * 16, 264);
                to_tf32(bW);
                wmma::mma_sync(acc[j], aO[kk], bW, acc[j]);
            }
        }
    }

    // ---- Epilogue: acc -> smem (reuse sKV), residual add, coalesced store ----
    __syncthreads();
    float* myAcc = sKV + warp * 16 * LDA;
#pragma unroll
    for (int j = 0; j < 16; j++)
        wmma::store_matrix_sync(myAcc + j * 16, acc[j], LDA, wmma::mem_row_major);
    __syncthreads();

    for (int i = tid; i < CC * 16; i += THREADS) {
        int c = i >> 4, rw = i & 15, r = rw >> 2, w4 = rw & 3;
        size_t off = ((size_t)(b * CC + c) * HH + (h0 + r)) * WW + w0 + w4 * 4;
        float4 vx = *(const float4*)(x + off);
        float bias_o = __ldg(bo + c);
        int t0 = w4 * 16 + r * 4;
        const float* arow = sKV + c;
        float4 vo;
        vo.x = vx.x + arow[(t0 + 0) * LDA] + bias_o;
        vo.y = vx.y + arow[(t0 + 1) * LDA] + bias_o;
        vo.z = vx.z + arow[(t0 + 2) * LDA] + bias_o;
        vo.w = vx.w + arow[(t0 + 3) * LDA] + bias_o;
        *(float4*)(out + off) = vo;
    }
}

extern "C" void kernel_launch(void* const* d_in, const int* in_sizes, int n_in,
                              void* d_out, int out_size) {
    const float* x    = (const float*)d_in[0];
    const float* cond = (const float*)d_in[1];
    const float* n1w  = (const float*)d_in[2];
    const float* n2w  = (const float*)d_in[3];
    const float* wq   = (const float*)d_in[4];
    const float* bq   = (const float*)d_in[5];
    const float* wkv  = (const float*)d_in[6];
    const float* bkv  = (const float*)d_in[7];
    const float* wo   = (const float*)d_in[8];
    const float* bo   = (const float*)d_in[9];
    const float* btab = (const float*)d_in[10];
    float* out = (float*)d_out;

    int B = in_sizes[0] / (CC * HH * WW);

    cudaFuncSetAttribute(xattn_kernel, cudaFuncAttributeMaxDynamicSharedMemorySize, SMEM_BYTES);
    dim3 grid(WW / 16, HH / 4, B);
    xattn_kernel<<<grid, THREADS, SMEM_BYTES>>>(x, cond, n1w, n2w, wq, bq, wkv, bkv,
                                                wo, bo, btab, out);
}

// round 3
// speedup vs baseline: 2.3441x; 2.3441x over previous
#include <cuda_runtime.h>
#include <cuda_fp16.h>
#include <mma.h>
#include <cstdint>

using namespace nvcuda;

#define CC      256
#define NH      8
#define HD      32
#define TOK     96          // tokens per CTA = 6 windows
#define NWIN    6
#define THREADS 384         // 12 warps
#define LDA     264         // activation row stride (halfs)
#define LDW     40          // QH/KH/VH + weight stage stride (halfs)
#define LDP     24          // P stride (halfs)
#define LDC     20          // cvt scratch stride (floats)
#define SCALE   0.17677669529663687f

// ---- shared memory byte offsets ----
#define OFF_AQ   0           // half [96][264]  = 50688
#define OFF_AKV  50688       // half [96][264]  = 50688   (AQ+AKV reused as fp32 [96][264] epilogue)
#define OFF_WB0  101376      // half stage buf0 (20480)
#define OFF_WB1  121856      // half stage buf1 (20480)
#define OFF_QH   142336      // half [96][40] = 7680  (also reused for O_h)
#define OFF_KH   150016      // half [96][40]
#define OFF_VH   157696      // half [96][40]
#define OFF_P    165376      // half [6][16][24] = 4608
#define OFF_CVT  169984      // float [12][16][20] = 15360
#define OFF_B    185344      // float [16][16] = 1024
#define SMEM_BYTES 186368

__device__ __align__(16) __half g_wq[CC * CC];
__device__ __align__(16) __half g_wkv[CC * 2 * CC];
__device__ __align__(16) __half g_wo[CC * CC];

__global__ void prep_kernel(const float* __restrict__ wq, const float* __restrict__ wkv,
                            const float* __restrict__ wo) {
    for (int k = blockIdx.x * blockDim.x + threadIdx.x; k < 4 * CC * CC;
         k += gridDim.x * blockDim.x) {
        if (k < CC * CC)            g_wq[k] = __float2half(wq[k]);
        else if (k < 3 * CC * CC)   g_wkv[k - CC * CC] = __float2half(wkv[k - CC * CC]);
        else                        g_wo[k - 3 * CC * CC] = __float2half(wo[k - 3 * CC * CC]);
    }
}

// stage a [256 x 32] half slice (src row stride = srcld halfs) into dst with ld = LDW
static __device__ __forceinline__ void stage_w32(__half* dst, const __half* __restrict__ src,
                                                 int srcld) {
    for (int i = threadIdx.x; i < 1024; i += THREADS) {
        int r = i >> 2, j = (i & 3) * 8;
        *(uint4*)(dst + r * LDW + j) = *(const uint4*)(src + r * srcld + j);
    }
}
// stage wo rows [32 x 256] half into dst with ld = 264
static __device__ __forceinline__ void stage_wo(__half* dst, const __half* __restrict__ src) {
    for (int i = threadIdx.x; i < 1024; i += THREADS) {
        int r = i >> 5, j = (i & 31) * 8;
        *(uint4*)(dst + r * 264 + j) = *(const uint4*)(src + r * 256 + j);
    }
}

__global__ void __launch_bounds__(THREADS, 1)
xattn_kernel(const float* __restrict__ x, const float* __restrict__ cond,
             const float* __restrict__ n1w, const float* __restrict__ n2w,
             const float* __restrict__ bq, const float* __restrict__ bkv,
             const float* __restrict__ bo, const float* __restrict__ btab,
             float* __restrict__ out)
{
    extern __shared__ char sm[];
    __half* aQ  = (__half*)(sm + OFF_AQ);
    __half* aKV = (__half*)(sm + OFF_AKV);
    __half* wbuf[2] = { (__half*)(sm + OFF_WB0), (__half*)(sm + OFF_WB1) };
    __half* QH  = (__half*)(sm + OFF_QH);
    __half* KH  = (__half*)(sm + OFF_KH);
    __half* VH  = (__half*)(sm + OFF_VH);
    __half* sP  = (__half*)(sm + OFF_P);
    float*  sCvt = (float*)(sm + OFF_CVT);
    float*  sB   = (float*)(sm + OFF_B);
    float*  sEpi = (float*)sm;   // fp32 [96][264], reuses aQ+aKV after head loop

    const int tid = threadIdx.x, lane = tid & 31, warp = tid >> 5;
    const int rw = warp >> 1;          // row tile / window (0..5)
    const int ch = warp & 1;           // column half
    const int w0 = blockIdx.x * 24, h0 = blockIdx.y * 4, b = blockIdx.z;
    float* myCvt = sCvt + warp * (16 * LDC);

    // ---- load x -> aKV, cond -> aQ (fp16, token-major), 384B-contiguous per (c,row) ----
    for (int i = tid; i < CC * 24; i += THREADS) {
        int c = i / 24, rem = i - c * 24;
        int r = rem / 6, q = rem - r * 6;
        size_t off = ((size_t)(b * CC + c) * 384 + (h0 + r)) * 384 + w0 + q * 4;
        float4 vx = *(const float4*)(x + off);
        float4 vc = *(const float4*)(cond + off);
        int t0 = q * 16 + r * 4;
        aKV[(t0 + 0) * LDA + c] = __float2half(vx.x);
        aKV[(t0 + 1) * LDA + c] = __float2half(vx.y);
        aKV[(t0 + 2) * LDA + c] = __float2half(vx.z);
        aKV[(t0 + 3) * LDA + c] = __float2half(vx.w);
        aQ[(t0 + 0) * LDA + c] = __float2half(vc.x);
        aQ[(t0 + 1) * LDA + c] = __float2half(vc.y);
        aQ[(t0 + 2) * LDA + c] = __float2half(vc.z);
        aQ[(t0 + 3) * LDA + c] = __float2half(vc.w);
    }
    // relative-position bias table (16x16)
    for (int i = tid; i < 256; i += THREADS) {
        int n = i >> 4, m = i & 15;
        int dr = (n >> 2) - (m >> 2) + 3;
        int dc = (n & 3) - (m & 3) + 3;
        sB[i] = __ldg(btab + dr * 7 + dc);
    }
    __syncthreads();

    // ---- LayerNorm: 192 rows (96 q + 96 kv), 2 threads per row ----
    {
        int row = tid >> 1, hf = tid & 1;
        __half* rp = (row < TOK) ? (aQ + row * LDA) : (aKV + (row - TOK) * LDA);
        const float* nw = (row < TOK) ? n1w : n2w;
        int c0 = hf * 128;
        float s = 0.f, s2 = 0.f;
#pragma unroll 8
        for (int c = 0; c < 128; c++) {
            float v = __half2float(rp[c0 + c]);
            s += v; s2 += v * v;
        }
        s  += __shfl_xor_sync(0xffffffffu, s, 1);
        s2 += __shfl_xor_sync(0xffffffffu, s2, 1);
        float mean = s * (1.0f / CC);
        float var  = s2 * (1.0f / CC) - mean * mean;
        float rstd = rsqrtf(var + 1e-5f);
#pragma unroll 8
        for (int c = 0; c < 128; c++) {
            float v = __half2float(rp[c0 + c]);
            rp[c0 + c] = __float2half((v - mean) * rstd * __ldg(nw + c0 + c));
        }
    }

    // ---- persistent output accumulators: warp covers rows rw*16, cols ch*128..+128 ----
    wmma::fragment<wmma::accumulator, 16, 16, 16, float> acc[8];
#pragma unroll
    for (int j = 0; j < 8; j++) wmma::fill_fragment(acc[j], 0.0f);

    // prefetch substage 0 (wq head 0 -> buf0)
    stage_w32(wbuf[0], g_wq, CC);

    for (int g = 0; g < 4 * NH; g++) {
        const int h = g >> 2, s = g & 3;
        __half* cur = wbuf[g & 1];
        __syncthreads();   // staged buffer ready; previous compute done

        // issue next stage (overlaps with this substage's compute)
        int g1 = g + 1;
        if (g1 < 4 * NH) {
            int h1 = g1 >> 2, s1 = g1 & 3;
            __half* nxt = wbuf[g1 & 1];
            if (s1 == 0)      stage_w32(nxt, g_wq + h1 * HD, CC);
            else if (s1 == 1) stage_w32(nxt, g_wkv + h1 * HD, 2 * CC);
            else if (s1 == 2) stage_w32(nxt, g_wkv + CC + h1 * HD, 2 * CC);
            else              stage_wo(nxt, g_wo + h1 * HD * CC);
        }

        if (s < 3) {
            // ---- projection: [16,16] tile per warp, K = 256 ----
            const __half* A = ((s == 0) ? aQ : aKV) + rw * 16 * LDA;
            wmma::fragment<wmma::accumulator, 16, 16, 16, float> pc;
            wmma::fill_fragment(pc, 0.0f);
#pragma unroll
            for (int kk = 0; kk < 16; kk++) {
                wmma::fragment<wmma::matrix_a, 16, 16, 16, __half, wmma::row_major> a;
                wmma::load_matrix_sync(a, A + kk * 16, LDA);
                wmma::fragment<wmma::matrix_b, 16, 16, 16, __half, wmma::row_major> bw;
                wmma::load_matrix_sync(bw, cur + kk * 16 * LDW + ch * 16, LDW);
                wmma::mma_sync(pc, a, bw, pc);
            }
            __syncwarp();
            wmma::store_matrix_sync(myCvt, pc, LDC, wmma::mem_row_major);
            __syncwarp();
            // convert + bias -> fp16 staging
            const float* bias = (s == 0) ? (bq + h * HD)
                              : (s == 1) ? (bkv + h * HD)
                                         : (bkv + CC + h * HD);
            __half* dst = (s == 0) ? QH : (s == 1) ? KH : VH;
            int r = lane >> 1, c0 = (lane & 1) * 8;
            const float* sr = myCvt + r * LDC + c0;
            __half* dp = dst + (rw * 16 + r) * LDW + ch * 16 + c0;
#pragma unroll
            for (int cc = 0; cc < 8; cc++)
                dp[cc] = __float2half(sr[cc] + __ldg(bias + ch * 16 + c0 + cc));
        } else {
            // ---- attention for window rw ----
            const int win = rw;
            if (ch == 0) {
                // scores = Qh @ Kh^T  (even warp of pair only)
                wmma::fragment<wmma::accumulator, 16, 16, 16, float> sc;
                wmma::fill_fragment(sc, 0.0f);
#pragma unroll
                for (int kk = 0; kk < 2; kk++) {
                    wmma::fragment<wmma::matrix_a, 16, 16, 16, __half, wmma::row_major> a;
                    wmma::load_matrix_sync(a, QH + win * 16 * LDW + kk * 16, LDW);
                    wmma::fragment<wmma::matrix_b, 16, 16, 16, __half, wmma::col_major> bk;
                    wmma::load_matrix_sync(bk, KH + win * 16 * LDW + kk * 16, LDW);
                    wmma::mma_sync(sc, a, bk, sc);
                }
                __syncwarp();
                wmma::store_matrix_sync(myCvt, sc, LDC, wmma::mem_row_major);
                __syncwarp();
                if (lane < 16) {
                    const float* srow = myCvt + lane * LDC;
                    const float* brow = sB + lane * 16;
                    float v[16], mx = -1e30f;
#pragma unroll
                    for (int m = 0; m < 16; m++) {
                        v[m] = srow[m] * SCALE + brow[m];
                        mx = fmaxf(mx, v[m]);
                    }
                    float sum = 0.f;
#pragma unroll
                    for (int m = 0; m < 16; m++) { v[m] = __expf(v[m] - mx); sum += v[m]; }
                    float inv = 1.0f / sum;
                    __half* prow = sP + (win * 16 + lane) * LDP;
#pragma unroll
                    for (int m = 0; m < 16; m++) prow[m] = __float2half(v[m] * inv);
                }
            }
            __syncthreads();
            // O_h = P @ Vh  (both warps, one 16x16 tile each)
            {
                wmma::fragment<wmma::accumulator, 16, 16, 16, float> oc;
                wmma::fill_fragment(oc, 0.0f);
                wmma::fragment<wmma::matrix_a, 16, 16, 16, __half, wmma::row_major> a;
                wmma::load_matrix_sync(a, sP + win * 16 * LDP, LDP);
                wmma::fragment<wmma::matrix_b, 16, 16, 16, __half, wmma::row_major> bv;
                wmma::load_matrix_sync(bv, VH + win * 16 * LDW + ch * 16, LDW);
                wmma::mma_sync(oc, a, bv, oc);
                __syncwarp();
                wmma::store_matrix_sync(myCvt, oc, LDC, wmma::mem_row_major);
                __syncwarp();
                int r = lane >> 1, c0 = (lane & 1) * 8;
                const float* sr = myCvt + r * LDC + c0;
                __half* dp = QH + (win * 16 + r) * LDW + ch * 16 + c0;  // O_h over QH
#pragma unroll
                for (int cc = 0; cc < 8; cc++) dp[cc] = __float2half(sr[cc]);
            }
            __syncthreads();
            // acc += O_h @ wo_h   (B from staged wo [32][264])
            wmma::fragment<wmma::matrix_a, 16, 16, 16, __half, wmma::row_major> aO0, aO1;
            wmma::load_matrix_sync(aO0, QH + rw * 16 * LDW + 0, LDW);
            wmma::load_matrix_sync(aO1, QH + rw * 16 * LDW + 16, LDW);
#pragma unroll
            for (int j = 0; j < 8; j++) {
                wmma::fragment<wmma::matrix_b, 16, 16, 16, __half, wmma::row_major> bw;
                wmma::load_matrix_sync(bw, cur + ch * 128 + j * 16, 264);
                wmma::mma_sync(acc[j], aO0, bw, acc[j]);
                wmma::load_matrix_sync(bw, cur + 16 * 264 + ch * 128 + j * 16, 264);
                wmma::mma_sync(acc[j], aO1, bw, acc[j]);
            }
        }
    }

    // ---- epilogue: acc -> fp32 smem (reuses activation region), residual add ----
    __syncthreads();
#pragma unroll
    for (int j = 0; j < 8; j++)
        wmma::store_matrix_sync(sEpi + rw * 16 * LDA + ch * 128 + j * 16, acc[j],
                                LDA, wmma::mem_row_major);
    __syncthreads();

    for (int i = tid; i < CC * 24; i += THREADS) {
        int c = i / 24, rem = i - c * 24;
        int r = rem / 6, q = rem - r * 6;
        size_t off = ((size_t)(b * CC + c) * 384 + (h0 + r)) * 384 + w0 + q * 4;
        float4 vx = *(const float4*)(x + off);
        float bias_o = __ldg(bo + c);
        int t0 = q * 16 + r * 4;
        const float* ar = sEpi + c;
        float4 vo;
        vo.x = vx.x + ar[(t0 + 0) * LDA] + bias_o;
        vo.y = vx.y + ar[(t0 + 1) * LDA] + bias_o;
        vo.z = vx.z + ar[(t0 + 2) * LDA] + bias_o;
        vo.w = vx.w + ar[(t0 + 3) * LDA] + bias_o;
        *(float4*)(out + off) = vo;
    }
}

extern "C" void kernel_launch(void* const* d_in, const int* in_sizes, int n_in,
                              void* d_out, int out_size) {
    const float* x    = (const float*)d_in[0];
    const float* cond = (const float*)d_in[1];
    const float* n1w  = (const float*)d_in[2];
    const float* n2w  = (const float*)d_in[3];
    const float* wq   = (const float*)d_in[4];
    const float* bq   = (const float*)d_in[5];
    const float* wkv  = (const float*)d_in[6];
    const float* bkv  = (const float*)d_in[7];
    const float* wo   = (const float*)d_in[8];
    const float* bo   = (const float*)d_in[9];
    const float* btab = (const float*)d_in[10];
    float* out = (float*)d_out;

    int B = in_sizes[0] / (CC * 384 * 384);

    prep_kernel<<<256, 512>>>(wq, wkv, wo);

    cudaFuncSetAttribute(xattn_kernel, cudaFuncAttributeMaxDynamicSharedMemorySize, SMEM_BYTES);
    dim3 grid(384 / 24, 384 / 4, B);
    xattn_kernel<<<grid, THREADS, SMEM_BYTES>>>(x, cond, n1w, n2w, bq, bkv, bo, btab, out);
}

// round 4
// speedup vs baseline: 2.3480x; 1.0017x over previous
#include <cuda_runtime.h>
#include <cuda_fp16.h>
#include <mma.h>
#include <cstdint>

using namespace nvcuda;

#define CC      256
#define NH      8
#define HD      32
#define TOK     96          // tokens per CTA = 6 windows
#define NWIN    6
#define THREADS 384         // 12 warps
#define LDA     264         // activation row stride (halfs)
#define LDW     40          // QH/KH/VH + weight stage stride (halfs)
#define LDP     24          // P stride (halfs)
#define LDC     20          // cvt scratch stride (floats)
#define SCALE   0.17677669529663687f

// ---- shared memory byte offsets ----
#define OFF_AQ   0           // half [96][264]  = 50688
#define OFF_AKV  50688       // half [96][264]  = 50688   (AQ+AKV reused as fp32 [96][264] epilogue)
#define OFF_WB0  101376      // half stage buf0 (20480)
#define OFF_WB1  121856      // half stage buf1 (20480)
#define OFF_QH   142336      // half [96][40] = 7680  (also reused for O_h)
#define OFF_KH   150016      // half [96][40]
#define OFF_VH   157696      // half [96][40]
#define OFF_P    165376      // half [6][16][24] = 4608
#define OFF_CVT  169984      // float [12][16][20] = 15360
#define OFF_B    185344      // float [16][16] = 1024
#define SMEM_BYTES 186368

__device__ __align__(16) __half g_wq[CC * CC];
__device__ __align__(16) __half g_wkv[CC * 2 * CC];
__device__ __align__(16) __half g_wo[CC * CC];

__global__ void prep_kernel(const float* __restrict__ wq, const float* __restrict__ wkv,
                            const float* __restrict__ wo) {
    for (int k = blockIdx.x * blockDim.x + threadIdx.x; k < 4 * CC * CC;
         k += gridDim.x * blockDim.x) {
        if (k < CC * CC)            g_wq[k] = __float2half(wq[k]);
        else if (k < 3 * CC * CC)   g_wkv[k - CC * CC] = __float2half(wkv[k - CC * CC]);
        else                        g_wo[k - 3 * CC * CC] = __float2half(wo[k - 3 * CC * CC]);
    }
}

// stage a [256 x 32] half slice (src row stride = srcld halfs) into dst with ld = LDW
static __device__ __forceinline__ void stage_w32(__half* dst, const __half* __restrict__ src,
                                                 int srcld) {
    for (int i = threadIdx.x; i < 1024; i += THREADS) {
        int r = i >> 2, j = (i & 3) * 8;
        *(uint4*)(dst + r * LDW + j) = *(const uint4*)(src + r * srcld + j);
    }
}
// stage wo rows [32 x 256] half into dst with ld = 264
static __device__ __forceinline__ void stage_wo(__half* dst, const __half* __restrict__ src) {
    for (int i = threadIdx.x; i < 1024; i += THREADS) {
        int r = i >> 5, j = (i & 31) * 8;
        *(uint4*)(dst + r * 264 + j) = *(const uint4*)(src + r * 256 + j);
    }
}

__global__ void __launch_bounds__(THREADS, 1)
xattn_kernel(const float* __restrict__ x, const float* __restrict__ cond,
             const float* __restrict__ n1w, const float* __restrict__ n2w,
             const float* __restrict__ bq, const float* __restrict__ bkv,
             const float* __restrict__ bo, const float* __restrict__ btab,
             float* __restrict__ out)
{
    extern __shared__ char sm[];
    __half* aQ  = (__half*)(sm + OFF_AQ);
    __half* aKV = (__half*)(sm + OFF_AKV);
    __half* wbuf[2] = { (__half*)(sm + OFF_WB0), (__half*)(sm + OFF_WB1) };
    __half* QH  = (__half*)(sm + OFF_QH);
    __half* KH  = (__half*)(sm + OFF_KH);
    __half* VH  = (__half*)(sm + OFF_VH);
    __half* sP  = (__half*)(sm + OFF_P);
    float*  sCvt = (float*)(sm + OFF_CVT);
    float*  sB   = (float*)(sm + OFF_B);
    float*  sEpi = (float*)sm;   // fp32 [96][264], reuses aQ+aKV after head loop

    const int tid = threadIdx.x, lane = tid & 31, warp = tid >> 5;
    const int rw = warp >> 1;          // row tile / window (0..5)
    const int ch = warp & 1;           // column half
    const int w0 = blockIdx.x * 24, h0 = blockIdx.y * 4, b = blockIdx.z;
    float* myCvt = sCvt + warp * (16 * LDC);

    // ---- load x -> aKV, cond -> aQ (fp16, token-major), 384B-contiguous per (c,row) ----
    for (int i = tid; i < CC * 24; i += THREADS) {
        int c = i / 24, rem = i - c * 24;
        int r = rem / 6, q = rem - r * 6;
        size_t off = ((size_t)(b * CC + c) * 384 + (h0 + r)) * 384 + w0 + q * 4;
        float4 vx = *(const float4*)(x + off);
        float4 vc = *(const float4*)(cond + off);
        int t0 = q * 16 + r * 4;
        aKV[(t0 + 0) * LDA + c] = __float2half(vx.x);
        aKV[(t0 + 1) * LDA + c] = __float2half(vx.y);
        aKV[(t0 + 2) * LDA + c] = __float2half(vx.z);
        aKV[(t0 + 3) * LDA + c] = __float2half(vx.w);
        aQ[(t0 + 0) * LDA + c] = __float2half(vc.x);
        aQ[(t0 + 1) * LDA + c] = __float2half(vc.y);
        aQ[(t0 + 2) * LDA + c] = __float2half(vc.z);
        aQ[(t0 + 3) * LDA + c] = __float2half(vc.w);
    }
    // relative-position bias table (16x16)
    for (int i = tid; i < 256; i += THREADS) {
        int n = i >> 4, m = i & 15;
        int dr = (n >> 2) - (m >> 2) + 3;
        int dc = (n & 3) - (m & 3) + 3;
        sB[i] = __ldg(btab + dr * 7 + dc);
    }
    __syncthreads();

    // ---- LayerNorm: 192 rows (96 q + 96 kv), 2 threads per row ----
    {
        int row = tid >> 1, hf = tid & 1;
        __half* rp = (row < TOK) ? (aQ + row * LDA) : (aKV + (row - TOK) * LDA);
        const float* nw = (row < TOK) ? n1w : n2w;
        int c0 = hf * 128;
        float s = 0.f, s2 = 0.f;
#pragma unroll 8
        for (int c = 0; c < 128; c++) {
            float v = __half2float(rp[c0 + c]);
            s += v; s2 += v * v;
        }
        s  += __shfl_xor_sync(0xffffffffu, s, 1);
        s2 += __shfl_xor_sync(0xffffffffu, s2, 1);
        float mean = s * (1.0f / CC);
        float var  = s2 * (1.0f / CC) - mean * mean;
        float rstd = rsqrtf(var + 1e-5f);
#pragma unroll 8
        for (int c = 0; c < 128; c++) {
            float v = __half2float(rp[c0 + c]);
            rp[c0 + c] = __float2half((v - mean) * rstd * __ldg(nw + c0 + c));
        }
    }

    // ---- persistent output accumulators: warp covers rows rw*16, cols ch*128..+128 ----
    wmma::fragment<wmma::accumulator, 16, 16, 16, float> acc[8];
#pragma unroll
    for (int j = 0; j < 8; j++) wmma::fill_fragment(acc[j], 0.0f);

    // prefetch substage 0 (wq head 0 -> buf0)
    stage_w32(wbuf[0], g_wq, CC);

    for (int g = 0; g < 4 * NH; g++) {
        const int h = g >> 2, s = g & 3;
        __half* cur = wbuf[g & 1];
        __syncthreads();   // staged buffer ready; previous compute done

        // issue next stage (overlaps with this substage's compute)
        int g1 = g + 1;
        if (g1 < 4 * NH) {
            int h1 = g1 >> 2, s1 = g1 & 3;
            __half* nxt = wbuf[g1 & 1];
            if (s1 == 0)      stage_w32(nxt, g_wq + h1 * HD, CC);
            else if (s1 == 1) stage_w32(nxt, g_wkv + h1 * HD, 2 * CC);
            else if (s1 == 2) stage_w32(nxt, g_wkv + CC + h1 * HD, 2 * CC);
            else              stage_wo(nxt, g_wo + h1 * HD * CC);
        }

        if (s < 3) {
            // ---- projection: [16,16] tile per warp, K = 256 ----
            const __half* A = ((s == 0) ? aQ : aKV) + rw * 16 * LDA;
            wmma::fragment<wmma::accumulator, 16, 16, 16, float> pc;
            wmma::fill_fragment(pc, 0.0f);
#pragma unroll
            for (int kk = 0; kk < 16; kk++) {
                wmma::fragment<wmma::matrix_a, 16, 16, 16, __half, wmma::row_major> a;
                wmma::load_matrix_sync(a, A + kk * 16, LDA);
                wmma::fragment<wmma::matrix_b, 16, 16, 16, __half, wmma::row_major> bw;
                wmma::load_matrix_sync(bw, cur + kk * 16 * LDW + ch * 16, LDW);
                wmma::mma_sync(pc, a, bw, pc);
            }
            __syncwarp();
            wmma::store_matrix_sync(myCvt, pc, LDC, wmma::mem_row_major);
            __syncwarp();
            // convert + bias -> fp16 staging
            const float* bias = (s == 0) ? (bq + h * HD)
                              : (s == 1) ? (bkv + h * HD)
                                         : (bkv + CC + h * HD);
            __half* dst = (s == 0) ? QH : (s == 1) ? KH : VH;
            int r = lane >> 1, c0 = (lane & 1) * 8;
            const float* sr = myCvt + r * LDC + c0;
            __half* dp = dst + (rw * 16 + r) * LDW + ch * 16 + c0;
#pragma unroll
            for (int cc = 0; cc < 8; cc++)
                dp[cc] = __float2half(sr[cc] + __ldg(bias + ch * 16 + c0 + cc));
        } else {
            // ---- attention for window rw ----
            const int win = rw;
            if (ch == 0) {
                // scores = Qh @ Kh^T  (even warp of pair only)
                wmma::fragment<wmma::accumulator, 16, 16, 16, float> sc;
                wmma::fill_fragment(sc, 0.0f);
#pragma unroll
                for (int kk = 0; kk < 2; kk++) {
                    wmma::fragment<wmma::matrix_a, 16, 16, 16, __half, wmma::row_major> a;
                    wmma::load_matrix_sync(a, QH + win * 16 * LDW + kk * 16, LDW);
                    wmma::fragment<wmma::matrix_b, 16, 16, 16, __half, wmma::col_major> bk;
                    wmma::load_matrix_sync(bk, KH + win * 16 * LDW + kk * 16, LDW);
                    wmma::mma_sync(sc, a, bk, sc);
                }
                __syncwarp();
                wmma::store_matrix_sync(myCvt, sc, LDC, wmma::mem_row_major);
                __syncwarp();
                if (lane < 16) {
                    const float* srow = myCvt + lane * LDC;
                    const float* brow = sB + lane * 16;
                    float v[16], mx = -1e30f;
#pragma unroll
                    for (int m = 0; m < 16; m++) {
                        v[m] = srow[m] * SCALE + brow[m];
                        mx = fmaxf(mx, v[m]);
                    }
                    float sum = 0.f;
#pragma unroll
                    for (int m = 0; m < 16; m++) { v[m] = __expf(v[m] - mx); sum += v[m]; }
                    float inv = 1.0f / sum;
                    __half* prow = sP + (win * 16 + lane) * LDP;
#pragma unroll
                    for (int m = 0; m < 16; m++) prow[m] = __float2half(v[m] * inv);
                }
            }
            __syncthreads();
            // O_h = P @ Vh  (both warps, one 16x16 tile each)
            {
                wmma::fragment<wmma::accumulator, 16, 16, 16, float> oc;
                wmma::fill_fragment(oc, 0.0f);
                wmma::fragment<wmma::matrix_a, 16, 16, 16, __half, wmma::row_major> a;
                wmma::load_matrix_sync(a, sP + win * 16 * LDP, LDP);
                wmma::fragment<wmma::matrix_b, 16, 16, 16, __half, wmma::row_major> bv;
                wmma::load_matrix_sync(bv, VH + win * 16 * LDW + ch * 16, LDW);
                wmma::mma_sync(oc, a, bv, oc);
                __syncwarp();
                wmma::store_matrix_sync(myCvt, oc, LDC, wmma::mem_row_major);
                __syncwarp();
                int r = lane >> 1, c0 = (lane & 1) * 8;
                const float* sr = myCvt + r * LDC + c0;
                __half* dp = QH + (win * 16 + r) * LDW + ch * 16 + c0;  // O_h over QH
#pragma unroll
                for (int cc = 0; cc < 8; cc++) dp[cc] = __float2half(sr[cc]);
            }
            __syncthreads();
            // acc += O_h @ wo_h   (B from staged wo [32][264])
            wmma::fragment<wmma::matrix_a, 16, 16, 16, __half, wmma::row_major> aO0, aO1;
            wmma::load_matrix_sync(aO0, QH + rw * 16 * LDW + 0, LDW);
            wmma::load_matrix_sync(aO1, QH + rw * 16 * LDW + 16, LDW);
#pragma unroll
            for (int j = 0; j < 8; j++) {
                wmma::fragment<wmma::matrix_b, 16, 16, 16, __half, wmma::row_major> bw;
                wmma::load_matrix_sync(bw, cur + ch * 128 + j * 16, 264);
                wmma::mma_sync(acc[j], aO0, bw, acc[j]);
                wmma::load_matrix_sync(bw, cur + 16 * 264 + ch * 128 + j * 16, 264);
                wmma::mma_sync(acc[j], aO1, bw, acc[j]);
            }
        }
    }

    // ---- epilogue: acc -> fp32 smem (reuses activation region), residual add ----
    __syncthreads();
#pragma unroll
    for (int j = 0; j < 8; j++)
        wmma::store_matrix_sync(sEpi + rw * 16 * LDA + ch * 128 + j * 16, acc[j],
                                LDA, wmma::mem_row_major);
    __syncthreads();

    for (int i = tid; i < CC * 24; i += THREADS) {
        int c = i / 24, rem = i - c * 24;
        int r = rem / 6, q = rem - r * 6;
        size_t off = ((size_t)(b * CC + c) * 384 + (h0 + r)) * 384 + w0 + q * 4;
        float4 vx = *(const float4*)(x + off);
        float bias_o = __ldg(bo + c);
        int t0 = q * 16 + r * 4;
        const float* ar = sEpi + c;
        float4 vo;
        vo.x = vx.x + ar[(t0 + 0) * LDA] + bias_o;
        vo.y = vx.y + ar[(t0 + 1) * LDA] + bias_o;
        vo.z = vx.z + ar[(t0 + 2) * LDA] + bias_o;
        vo.w = vx.w + ar[(t0 + 3) * LDA] + bias_o;
        *(float4*)(out + off) = vo;
    }
}

extern "C" void kernel_launch(void* const* d_in, const int* in_sizes, int n_in,
                              void* d_out, int out_size) {
    const float* x    = (const float*)d_in[0];
    const float* cond = (const float*)d_in[1];
    const float* n1w  = (const float*)d_in[2];
    const float* n2w  = (const float*)d_in[3];
    const float* wq   = (const float*)d_in[4];
    const float* bq   = (const float*)d_in[5];
    const float* wkv  = (const float*)d_in[6];
    const float* bkv  = (const float*)d_in[7];
    const float* wo   = (const float*)d_in[8];
    const float* bo   = (const float*)d_in[9];
    const float* btab = (const float*)d_in[10];
    float* out = (float*)d_out;

    int B = in_sizes[0] / (CC * 384 * 384);

    prep_kernel<<<256, 512>>>(wq, wkv, wo);

    cudaFuncSetAttribute(xattn_kernel, cudaFuncAttributeMaxDynamicSharedMemorySize, SMEM_BYTES);
    dim3 grid(384 / 24, 384 / 4, B);
    xattn_kernel<<<grid, THREADS, SMEM_BYTES>>>(x, cond, n1w, n2w, bq, bkv, bo, btab, out);
}

// round 9
// speedup vs baseline: 4.2893x; 1.8268x over previous
#include <cuda_runtime.h>
#include <cuda_fp16.h>
#include <mma.h>
#include <cstdint>

namespace wm = nvcuda::wmma;
#define THREADS 256
#define SCALE 0.17677669529663687f

#define OFF_ACT  0
#define OFF_QH   67584
#define OFF_D0   135168
#define OFF_D1   153600
#define OFF_KVH  172032
#define OFF_OH   190464
#define OFF_P    208896
#define OFF_SCR  221184
#define SMEM_BYTES 231424

typedef wm::fragment<wm::matrix_a, 16, 16, 16, __half, wm::row_major> FA;
typedef wm::fragment<wm::matrix_b, 16, 16, 16, __half, wm::row_major> FBr;
typedef wm::fragment<wm::matrix_b, 16, 16, 16, __half, wm::col_major> FBc;
typedef wm::fragment<wm::accumulator, 16, 16, 16, float> FC;

// 32 uniform slots of 9216 halfs.
// 0-7: wq chunk [32k][264n]; 8+6p+s: s0,s1 K [128k][72n]; s2,s3 V; s4,s5 wo [32k][264n]
__device__ __align__(16) __half g_stage[32 * 9216];

__global__ void prep_kernel(const float* __restrict__ wq, const float* __restrict__ wkv,
                            const float* __restrict__ wo) {
    int idx = blockIdx.x * blockDim.x + threadIdx.x;
    if (idx >= 32 * 9216) return;
    int item = idx / 9216, rem = idx % 9216;
    float v = 0.f;
    if (item < 8) {
        if (rem < 8448) { int kk = rem / 264, n = rem % 264;
            if (n < 256) v = wq[(item * 32 + kk) * 256 + n]; }
    } else {
        int t = item - 8, p = t / 6, s = t % 6;
        if (s < 4) {
            int kk = rem / 72, n = rem % 72;
            if (n < 64) {
                int k = (s & 1) * 128 + kk;
                int col = (s < 2) ? (64 * p + n) : (256 + 64 * p + n);
                v = wkv[k * 512 + col];
            }
        } else if (rem < 8448) {
            int kk = rem / 264, n = rem % 264;
            if (n < 256) v = wo[(64 * p + (s - 4) * 32 + kk) * 256 + n];
        }
    }
    g_stage[idx] = __float2half(v);
}

static __device__ __forceinline__ uint32_t s2u(const void* p) {
    uint32_t a;
    asm("{ .reg .u64 t; cvta.to.shared.u64 t, %1; cvt.u32.u64 %0, t; }" : "=r"(a) : "l"(p));
    return a;
}
#define CPCOMMIT() asm volatile("cp.async.commit_group;")
#define CPWAIT1()  asm volatile("cp.async.wait_group 1;")
#define CPWAIT0()  asm volatile("cp.async.wait_group 0;")

static __device__ void issue(int item, uint32_t sb) {
    uint32_t dst = sb + ((item & 1) ? OFF_D1 : OFF_D0);
    const char* src = (const char*)(g_stage + (size_t)item * 9216);
    for (int o = threadIdx.x * 16; o < 18432; o += THREADS * 16)
        asm volatile("cp.async.cg.shared.global [%0], [%1], 16;" :: "r"(dst + o), "l"(src + o));
    CPCOMMIT();
}

static __device__ void wb16(const FC& c, float* scr, __half* dst, int ldst,
                            const float* bias, int bcol) {
    wm::store_matrix_sync(scr, c, 20, wm::mem_row_major);
    __syncwarp();
    int lane = threadIdx.x & 31, r = lane >> 1, c0 = (lane & 1) * 8;
    __half hh[8];
#pragma unroll
    for (int e = 0; e < 8; e++) {
        float v = scr[r * 20 + c0 + e];
        if (bias) v += __ldg(bias + bcol + c0 + e);
        hh[e] = __float2half(v);
    }
    *(uint4*)(dst + r * ldst + c0) = *(uint4*)hh;
    __syncwarp();
}

static __device__ void load_ln(const float* __restrict__ src, __half* ACT,
                               const float* __restrict__ nw, int w0, int h0, int b) {
    for (int i = threadIdx.x; i < 8192; i += THREADS) {
        int c = i >> 5, rem = i & 31, r = rem >> 3, q = rem & 7;
        size_t off = ((size_t)(b * 256 + c) * 384 + (h0 + r)) * 384 + w0 + q * 4;
        float4 v = *(const float4*)(src + off);
        int t0 = q * 16 + r * 4;
        ACT[(t0 + 0) * 264 + c] = __float2half(v.x);
        ACT[(t0 + 1) * 264 + c] = __float2half(v.y);
        ACT[(t0 + 2) * 264 + c] = __float2half(v.z);
        ACT[(t0 + 3) * 264 + c] = __float2half(v.w);
    }
    __syncthreads();
    int row = threadIdx.x >> 1, c0 = (threadIdx.x & 1) * 128;
    __half* rp = ACT + row * 264 + c0;
    float s = 0.f, s2 = 0.f;
#pragma unroll 4
    for (int j = 0; j < 16; j++) {
        uint4 u = *(uint4*)(rp + j * 8);
        __half* hp = (__half*)&u;
#pragma unroll
        for (int e = 0; e < 8; e++) { float v = __half2float(hp[e]); s += v; s2 += v * v; }
    }
    s  += __shfl_xor_sync(0xffffffffu, s, 1);
    s2 += __shfl_xor_sync(0xffffffffu, s2, 1);
    float mean = s * (1.f / 256.f), var = s2 * (1.f / 256.f) - mean * mean;
    float rstd = rsqrtf(var + 1e-5f);
#pragma unroll 4
    for (int j = 0; j < 16; j++) {
        uint4 u = *(uint4*)(rp + j * 8);
        __half* hp = (__half*)&u;
#pragma unroll
        for (int e = 0; e < 8; e++)
            hp[e] = __float2half((__half2float(hp[e]) - mean) * rstd * __ldg(nw + c0 + j * 8 + e));
        *(uint4*)(rp + j * 8) = u;
    }
}

__global__ void __launch_bounds__(THREADS, 1)
xattn_kernel(const float* __restrict__ x, const float* __restrict__ cond,
             const float* __restrict__ n1w, const float* __restrict__ n2w,
             const float* __restrict__ bq, const float* __restrict__ bkv,
             const float* __restrict__ bo, const float* __restrict__ btab,
             float* __restrict__ out)
{
    extern __shared__ char sm[];
    const int tid = threadIdx.x, lane = tid & 31, warp = tid >> 5;
    const int w0 = blockIdx.x * 32, h0 = blockIdx.y * 4, b = blockIdx.z;
    uint32_t sb = s2u(sm);
    __half* ACT = (__half*)(sm + OFF_ACT);
    __half* QH  = (__half*)(sm + OFF_QH);
    __half* KVH = (__half*)(sm + OFF_KVH);
    __half* OH  = (__half*)(sm + OFF_OH);
    __half* P   = (__half*)(sm + OFF_P);
    float* myscr = (float*)(sm + OFF_SCR) + warp * 320;
    const __half* DB[2] = { (const __half*)(sm + OFF_D0), (const __half*)(sm + OFF_D1) };

    int nit = 2;
    issue(0, sb); issue(1, sb);

    load_ln(cond, ACT, n1w, w0, h0, b);
    __syncthreads();

    const int mr = warp >> 2, nc = warp & 3;      // 64x64 tiling (Q, O)
    const int mrk = warp >> 1, nck = warp & 1;    // 32x32 tiling (K, V)

    // ===== Q projection =====
    {
        FC qa[16];
#pragma unroll
        for (int f = 0; f < 16; f++) wm::fill_fragment(qa[f], 0.0f);
        for (int kc = 0; kc < 8; kc++) {
            CPWAIT1(); __syncthreads();
            const __half* buf = DB[kc & 1];
#pragma unroll
            for (int s2 = 0; s2 < 2; s2++) {
                FA a4[4]; FBr b4[4];
#pragma unroll
                for (int i = 0; i < 4; i++)
                    wm::load_matrix_sync(a4[i], ACT + (mr * 64 + i * 16) * 264 + kc * 32 + s2 * 16, 264);
#pragma unroll
                for (int i = 0; i < 4; i++)
                    wm::load_matrix_sync(b4[i], buf + (s2 * 16) * 264 + nc * 64 + i * 16, 264);
#pragma unroll
                for (int fr = 0; fr < 4; fr++)
#pragma unroll
                    for (int fc = 0; fc < 4; fc++)
                        wm::mma_sync(qa[fr * 4 + fc], a4[fr], b4[fc], qa[fr * 4 + fc]);
            }
            __syncthreads();
            issue(nit, sb); nit++;
        }
#pragma unroll
        for (int f = 0; f < 16; f++) {
            int fr = f >> 2, fc = f & 3;
            wb16(qa[f], myscr, QH + (mr * 64 + fr * 16) * 264 + nc * 64 + fc * 16, 264,
                 bq, nc * 64 + fc * 16);
        }
    }
    __syncthreads();

    load_ln(x, ACT, n2w, w0, h0, b);
    __syncthreads();

    FC oacc[16];
#pragma unroll
    for (int f = 0; f < 16; f++) wm::fill_fragment(oacc[f], 0.0f);

    for (int p = 0; p < 4; p++) {
        // ---- K projection ----
        {
            FC ka[4];
#pragma unroll
            for (int f = 0; f < 4; f++) wm::fill_fragment(ka[f], 0.0f);
            for (int kr = 0; kr < 2; kr++) {
                CPWAIT1(); __syncthreads();
                const __half* buf = DB[kr];
#pragma unroll
                for (int s2 = 0; s2 < 8; s2++) {
                    FA a2[2]; FBr b2[2];
#pragma unroll
                    for (int i = 0; i < 2; i++)
                        wm::load_matrix_sync(a2[i], ACT + (mrk * 32 + i * 16) * 264 + kr * 128 + s2 * 16, 264);
#pragma unroll
                    for (int i = 0; i < 2; i++)
                        wm::load_matrix_sync(b2[i], buf + (s2 * 16) * 72 + nck * 32 + i * 16, 72);
#pragma unroll
                    for (int fr = 0; fr < 2; fr++)
#pragma unroll
                        for (int fc = 0; fc < 2; fc++)
                            wm::mma_sync(ka[fr * 2 + fc], a2[fr], b2[fc], ka[fr * 2 + fc]);
                }
                __syncthreads();
                issue(nit, sb); nit++;
            }
#pragma unroll
            for (int f = 0; f < 4; f++) {
                int fr = f >> 1, fc = f & 1;
                wb16(ka[f], myscr, KVH + (mrk * 32 + fr * 16) * 72 + nck * 32 + fc * 16, 72,
                     bkv, 64 * p + nck * 32 + fc * 16);
            }
        }
        __syncthreads();

        // ---- scores + softmax: warp = window, 2 heads ----
        for (int hh = 0; hh < 2; hh++) {
            FA a2[2]; FBc b2[2];
#pragma unroll
            for (int i = 0; i < 2; i++)
                wm::load_matrix_sync(a2[i], QH + (warp * 16) * 264 + (2 * p + hh) * 32 + i * 16, 264);
#pragma unroll
            for (int i = 0; i < 2; i++)
                wm::load_matrix_sync(b2[i], KVH + (warp * 16) * 72 + hh * 32 + i * 16, 72);
            FC sc;
            wm::fill_fragment(sc, 0.0f);
            wm::mma_sync(sc, a2[0], b2[0], sc);
            wm::mma_sync(sc, a2[1], b2[1], sc);
            wm::store_matrix_sync(myscr, sc, 20, wm::mem_row_major);
            __syncwarp();
            if (lane < 16) {
                float v[16], mx = -1e30f;
#pragma unroll
                for (int m = 0; m < 16; m++) {
                    int bi = ((lane >> 2) - (m >> 2) + 3) * 7 + ((lane & 3) - (m & 3) + 3);
                    v[m] = myscr[lane * 20 + m] * SCALE + __ldg(btab + bi);
                    mx = fmaxf(mx, v[m]);
                }
                float s = 0.f;
#pragma unroll
                for (int m = 0; m < 16; m++) { v[m] = __expf(v[m] - mx); s += v[m]; }
                float inv = 1.0f / s;
                __half* pr = P + hh * 3072 + (warp * 16 + lane) * 24;
#pragma unroll
                for (int m = 0; m < 16; m++) pr[m] = __float2half(v[m] * inv);
            }
            __syncwarp();
        }

        // ---- V projection (overwrites KVH) ----
        {
            FC va[4];
#pragma unroll
            for (int f = 0; f < 4; f++) wm::fill_fragment(va[f], 0.0f);
            for (int kr = 0; kr < 2; kr++) {
                CPWAIT1(); __syncthreads();
                const __half* buf = DB[kr];
#pragma unroll
                for (int s2 = 0; s2 < 8; s2++) {
                    FA a2[2]; FBr b2[2];
#pragma unroll
                    for (int i = 0; i < 2; i++)
                        wm::load_matrix_sync(a2[i], ACT + (mrk * 32 + i * 16) * 264 + kr * 128 + s2 * 16, 264);
#pragma unroll
                    for (int i = 0; i < 2; i++)
                        wm::load_matrix_sync(b2[i], buf + (s2 * 16) * 72 + nck * 32 + i * 16, 72);
#pragma unroll
                    for (int fr = 0; fr < 2; fr++)
#pragma unroll
                        for (int fc = 0; fc < 2; fc++)
                            wm::mma_sync(va[fr * 2 + fc], a2[fr], b2[fc], va[fr * 2 + fc]);
                }
                __syncthreads();
                issue(nit, sb); nit++;
            }
#pragma unroll
            for (int f = 0; f < 4; f++) {
                int fr = f >> 1, fc = f & 1;
                wb16(va[f], myscr, KVH + (mrk * 32 + fr * 16) * 72 + nck * 32 + fc * 16, 72,
                     bkv, 256 + 64 * p + nck * 32 + fc * 16);
            }
        }
        __syncthreads();

        // ---- PV: per-window, OH[128][64+pad] ----
        for (int hh = 0; hh < 2; hh++) {
            FA pa;
            wm::load_matrix_sync(pa, P + hh * 3072 + (warp * 16) * 24, 24);
#pragma unroll
            for (int i = 0; i < 2; i++) {
                FBr bv;
                wm::load_matrix_sync(bv, KVH + (warp * 16) * 72 + hh * 32 + i * 16, 72);
                FC oh;
                wm::fill_fragment(oh, 0.0f);
                wm::mma_sync(oh, pa, bv, oh);
                wb16(oh, myscr, OH + (warp * 16) * 72 + hh * 32 + i * 16, 72, nullptr, 0);
            }
        }

        // ---- O accumulation: oacc += OH @ wo_pair ----
        CPWAIT0(); __syncthreads();
#pragma unroll
        for (int kk = 0; kk < 4; kk++) {
            const __half* buf = DB[kk >> 1];
            FA a4[4]; FBr b4[4];
#pragma unroll
            for (int i = 0; i < 4; i++)
                wm::load_matrix_sync(a4[i], OH + (mr * 64 + i * 16) * 72 + kk * 16, 72);
#pragma unroll
            for (int i = 0; i < 4; i++)
                wm::load_matrix_sync(b4[i], buf + ((kk & 1) * 16) * 264 + nc * 64 + i * 16, 264);
#pragma unroll
            for (int fr = 0; fr < 4; fr++)
#pragma unroll
                for (int fc = 0; fc < 4; fc++)
                    wm::mma_sync(oacc[fr * 4 + fc], a4[fr], b4[fc], oacc[fr * 4 + fc]);
        }
        __syncthreads();
        if (nit < 32) { issue(nit, sb); issue(nit + 1, sb); nit += 2; }
    }

    // ===== epilogue =====
    float* ep = (float*)sm;   // [128][260] over ACT+QH
#pragma unroll
    for (int f = 0; f < 16; f++) {
        int fr = f >> 2, fc = f & 3;
        wm::store_matrix_sync(ep + (size_t)(mr * 64 + fr * 16) * 260 + nc * 64 + fc * 16,
                              oacc[f], 260, wm::mem_row_major);
    }
    __syncthreads();
    for (int i = tid; i < 8192; i += THREADS) {
        int c = i >> 5, rem = i & 31, r = rem >> 3, q = rem & 7;
        size_t off = ((size_t)(b * 256 + c) * 384 + (h0 + r)) * 384 + w0 + q * 4;
        float4 vx = *(const float4*)(x + off);
        float bias_o = __ldg(bo + c);
        int t0 = q * 16 + r * 4;
        float4 vo;
        vo.x = vx.x + ep[(size_t)(t0 + 0) * 260 + c] + bias_o;
        vo.y = vx.y + ep[(size_t)(t0 + 1) * 260 + c] + bias_o;
        vo.z = vx.z + ep[(size_t)(t0 + 2) * 260 + c] + bias_o;
        vo.w = vx.w + ep[(size_t)(t0 + 3) * 260 + c] + bias_o;
        *(float4*)(out + off) = vo;
    }
}

extern "C" void kernel_launch(void* const* d_in, const int* in_sizes, int n_in,
                              void* d_out, int out_size) {
    const float* x    = (const float*)d_in[0];
    const float* cond = (const float*)d_in[1];
    const float* n1w  = (const float*)d_in[2];
    const float* n2w  = (const float*)d_in[3];
    const float* wq   = (const float*)d_in[4];
    const float* bq   = (const float*)d_in[5];
    const float* wkv  = (const float*)d_in[6];
    const float* bkv  = (const float*)d_in[7];
    const float* wo   = (const float*)d_in[8];
    const float* bo   = (const float*)d_in[9];
    const float* btab = (const float*)d_in[10];
    float* out = (float*)d_out;

    int B = in_sizes[0] / (256 * 384 * 384);

    prep_kernel<<<1152, 256>>>(wq, wkv, wo);

    cudaFuncSetAttribute(xattn_kernel, cudaFuncAttributeMaxDynamicSharedMemorySize, SMEM_BYTES);
    dim3 grid(12, 96, B);
    xattn_kernel<<<grid, THREADS, SMEM_BYTES>>>(x, cond, n1w, n2w, bq, bkv, bo, btab, out);
}

// round 12
// speedup vs baseline: 5.0699x; 1.1820x over previous
#include <cuda_runtime.h>
#include <cuda_fp16.h>
#include <mma.h>
#include <cstdint>

namespace wm = nvcuda::wmma;
#define THREADS 256
#define SCALE 0.17677669529663687f

#define OFF_ACT  0
#define OFF_QH   67584
#define OFF_D0   135168
#define OFF_D1   153600
#define OFF_KVH  172032
#define OFF_OH   190464
#define OFF_P    208896
#define OFF_SCR  221184
#define SMEM_BYTES 231424

typedef wm::fragment<wm::matrix_a, 16, 16, 16, __half, wm::row_major> FA;
typedef wm::fragment<wm::matrix_b, 16, 16, 16, __half, wm::row_major> FBr;
typedef wm::fragment<wm::matrix_b, 16, 16, 16, __half, wm::col_major> FBc;
typedef wm::fragment<wm::accumulator, 16, 16, 16, float> FC;

// 32 uniform slots of 9216 halfs.
// 0-7: wq chunk [32k][264n]; 8+6p+s: s0,s1 K [128k][72n]; s2,s3 V; s4,s5 wo [32k][264n]
__device__ __align__(16) __half g_stage[32 * 9216];

__global__ void prep_kernel(const float* __restrict__ wq, const float* __restrict__ wkv,
                            const float* __restrict__ wo) {
    int idx = blockIdx.x * blockDim.x + threadIdx.x;
    if (idx >= 32 * 9216) return;
    int item = idx / 9216, rem = idx % 9216;
    float v = 0.f;
    if (item < 8) {
        if (rem < 8448) { int kk = rem / 264, n = rem % 264;
            if (n < 256) v = wq[(item * 32 + kk) * 256 + n]; }
    } else {
        int t = item - 8, p = t / 6, s = t % 6;
        if (s < 4) {
            int kk = rem / 72, n = rem % 72;
            if (n < 64) {
                int k = (s & 1) * 128 + kk;
                int col = (s < 2) ? (64 * p + n) : (256 + 64 * p + n);
                v = wkv[k * 512 + col];
            }
        } else if (rem < 8448) {
            int kk = rem / 264, n = rem % 264;
            if (n < 256) v = wo[(64 * p + (s - 4) * 32 + kk) * 256 + n];
        }
    }
    g_stage[idx] = __float2half(v);
}

static __device__ __forceinline__ uint32_t s2u(const void* p) {
    uint32_t a;
    asm("{ .reg .u64 t; cvta.to.shared.u64 t, %1; cvt.u32.u64 %0, t; }" : "=r"(a) : "l"(p));
    return a;
}
#define CPCOMMIT() asm volatile("cp.async.commit_group;")
#define CPWAIT1()  asm volatile("cp.async.wait_group 1;")
#define CPWAIT0()  asm volatile("cp.async.wait_group 0;")

static __device__ void issue(int item, uint32_t sb) {
    uint32_t dst = sb + ((item & 1) ? OFF_D1 : OFF_D0);
    const char* src = (const char*)(g_stage + (size_t)item * 9216);
    for (int o = threadIdx.x * 16; o < 18432; o += THREADS * 16)
        asm volatile("cp.async.cg.shared.global [%0], [%1], 16;" :: "r"(dst + o), "l"(src + o));
    CPCOMMIT();
}

static __device__ void wb16(const FC& c, float* scr, __half* dst, int ldst,
                            const float* bias, int bcol) {
    wm::store_matrix_sync(scr, c, 20, wm::mem_row_major);
    __syncwarp();
    int lane = threadIdx.x & 31, r = lane >> 1, c0 = (lane & 1) * 8;
    __half hh[8];
#pragma unroll
    for (int e = 0; e < 8; e++) {
        float v = scr[r * 20 + c0 + e];
        if (bias) v += __ldg(bias + bcol + c0 + e);
        hh[e] = __float2half(v);
    }
    *(uint4*)(dst + r * ldst + c0) = *(uint4*)hh;
    __syncwarp();
}

// conflict-free-ish transpose load: each lane buffers 8 channels x 4 tokens,
// then writes 16B token-major rows (2-way max bank conflict vs 16-way scalar).
static __device__ void load_ln(const float* __restrict__ src, __half* ACT,
                               const float* __restrict__ nw, int w0, int h0, int b) {
    const int lane = threadIdx.x & 31, warp = threadIdx.x >> 5;
    const int j = lane & 3, g = lane >> 2;
    for (int it = warp; it < 32; it += 8) {
        int c0 = (it >> 2) * 32, r = it & 3;
        int cbase = c0 + 8 * j;
        float4 buf[8];
#pragma unroll
        for (int s = 0; s < 8; s++)
            buf[s] = *(const float4*)(src +
                ((size_t)(b * 256 + cbase + s) * 384 + (h0 + r)) * 384 + w0 + 4 * g);
        int t0 = g * 16 + r * 4;
#pragma unroll
        for (int k = 0; k < 4; k++) {
            __half hh[8];
#pragma unroll
            for (int s = 0; s < 8; s++) {
                float v = (k == 0) ? buf[s].x : (k == 1) ? buf[s].y
                        : (k == 2) ? buf[s].z : buf[s].w;
                hh[s] = __float2half(v);
            }
            *(uint4*)(ACT + (t0 + k) * 264 + cbase) = *(uint4*)hh;
        }
    }
    __syncthreads();
    int row = threadIdx.x >> 1, c0 = (threadIdx.x & 1) * 128;
    __half* rp = ACT + row * 264 + c0;
    float s = 0.f, s2 = 0.f;
#pragma unroll 4
    for (int jj = 0; jj < 16; jj++) {
        uint4 u = *(uint4*)(rp + jj * 8);
        __half* hp = (__half*)&u;
#pragma unroll
        for (int e = 0; e < 8; e++) { float v = __half2float(hp[e]); s += v; s2 += v * v; }
    }
    s  += __shfl_xor_sync(0xffffffffu, s, 1);
    s2 += __shfl_xor_sync(0xffffffffu, s2, 1);
    float mean = s * (1.f / 256.f), var = s2 * (1.f / 256.f) - mean * mean;
    float rstd = rsqrtf(var + 1e-5f);
#pragma unroll 4
    for (int jj = 0; jj < 16; jj++) {
        uint4 u = *(uint4*)(rp + jj * 8);
        __half* hp = (__half*)&u;
#pragma unroll
        for (int e = 0; e < 8; e++)
            hp[e] = __float2half((__half2float(hp[e]) - mean) * rstd * __ldg(nw + c0 + jj * 8 + e));
        *(uint4*)(rp + jj * 8) = u;
    }
}

__global__ void __launch_bounds__(THREADS, 1)
xattn_kernel(const float* __restrict__ x, const float* __restrict__ cond,
             const float* __restrict__ n1w, const float* __restrict__ n2w,
             const float* __restrict__ bq, const float* __restrict__ bkv,
             const float* __restrict__ bo, const float* __restrict__ btab,
             float* __restrict__ out)
{
    extern __shared__ char sm[];
    const int tid = threadIdx.x, lane = tid & 31, warp = tid >> 5;
    const int w0 = blockIdx.x * 32, h0 = blockIdx.y * 4, b = blockIdx.z;
    uint32_t sb = s2u(sm);
    __half* ACT = (__half*)(sm + OFF_ACT);
    __half* QH  = (__half*)(sm + OFF_QH);
    __half* KVH = (__half*)(sm + OFF_KVH);
    __half* OH  = (__half*)(sm + OFF_OH);
    __half* P   = (__half*)(sm + OFF_P);
    float* myscr = (float*)(sm + OFF_SCR) + warp * 320;
    const __half* DB[2] = { (const __half*)(sm + OFF_D0), (const __half*)(sm + OFF_D1) };

    int nit = 2;
    issue(0, sb); issue(1, sb);

    load_ln(cond, ACT, n1w, w0, h0, b);
    __syncthreads();

    const int mr = warp >> 2, nc = warp & 3;      // 64x64 tiling (Q, O)
    const int mrk = warp >> 1, nck = warp & 1;    // 32x32 tiling (K, V)

    // ===== Q projection =====
    {
        FC qa[16];
#pragma unroll
        for (int f = 0; f < 16; f++) wm::fill_fragment(qa[f], 0.0f);
        for (int kc = 0; kc < 8; kc++) {
            CPWAIT1(); __syncthreads();
            const __half* buf = DB[kc & 1];
#pragma unroll
            for (int s2 = 0; s2 < 2; s2++) {
                FA a4[4]; FBr b4[4];
#pragma unroll
                for (int i = 0; i < 4; i++)
                    wm::load_matrix_sync(a4[i], ACT + (mr * 64 + i * 16) * 264 + kc * 32 + s2 * 16, 264);
#pragma unroll
                for (int i = 0; i < 4; i++)
                    wm::load_matrix_sync(b4[i], buf + (s2 * 16) * 264 + nc * 64 + i * 16, 264);
#pragma unroll
                for (int fr = 0; fr < 4; fr++)
#pragma unroll
                    for (int fc = 0; fc < 4; fc++)
                        wm::mma_sync(qa[fr * 4 + fc], a4[fr], b4[fc], qa[fr * 4 + fc]);
            }
            __syncthreads();
            issue(nit, sb); nit++;
        }
#pragma unroll
        for (int f = 0; f < 16; f++) {
            int fr = f >> 2, fc = f & 3;
            wb16(qa[f], myscr, QH + (mr * 64 + fr * 16) * 264 + nc * 64 + fc * 16, 264,
                 bq, nc * 64 + fc * 16);
        }
    }
    __syncthreads();

    load_ln(x, ACT, n2w, w0, h0, b);
    __syncthreads();

    FC oacc[16];
#pragma unroll
    for (int f = 0; f < 16; f++) wm::fill_fragment(oacc[f], 0.0f);

    for (int p = 0; p < 4; p++) {
        // ---- K projection ----
        {
            FC ka[4];
#pragma unroll
            for (int f = 0; f < 4; f++) wm::fill_fragment(ka[f], 0.0f);
            for (int kr = 0; kr < 2; kr++) {
                CPWAIT1(); __syncthreads();
                const __half* buf = DB[kr];
#pragma unroll
                for (int s2 = 0; s2 < 8; s2++) {
                    FA a2[2]; FBr b2[2];
#pragma unroll
                    for (int i = 0; i < 2; i++)
                        wm::load_matrix_sync(a2[i], ACT + (mrk * 32 + i * 16) * 264 + kr * 128 + s2 * 16, 264);
#pragma unroll
                    for (int i = 0; i < 2; i++)
                        wm::load_matrix_sync(b2[i], buf + (s2 * 16) * 72 + nck * 32 + i * 16, 72);
#pragma unroll
                    for (int fr = 0; fr < 2; fr++)
#pragma unroll
                        for (int fc = 0; fc < 2; fc++)
                            wm::mma_sync(ka[fr * 2 + fc], a2[fr], b2[fc], ka[fr * 2 + fc]);
                }
                __syncthreads();
                issue(nit, sb); nit++;
            }
#pragma unroll
            for (int f = 0; f < 4; f++) {
                int fr = f >> 1, fc = f & 1;
                wb16(ka[f], myscr, KVH + (mrk * 32 + fr * 16) * 72 + nck * 32 + fc * 16, 72,
                     bkv, 64 * p + nck * 32 + fc * 16);
            }
        }
        __syncthreads();

        // ---- scores + softmax: warp = window, 2 heads ----
        for (int hh = 0; hh < 2; hh++) {
            FA a2[2]; FBc b2[2];
#pragma unroll
            for (int i = 0; i < 2; i++)
                wm::load_matrix_sync(a2[i], QH + (warp * 16) * 264 + (2 * p + hh) * 32 + i * 16, 264);
#pragma unroll
            for (int i = 0; i < 2; i++)
                wm::load_matrix_sync(b2[i], KVH + (warp * 16) * 72 + hh * 32 + i * 16, 72);
            FC sc;
            wm::fill_fragment(sc, 0.0f);
            wm::mma_sync(sc, a2[0], b2[0], sc);
            wm::mma_sync(sc, a2[1], b2[1], sc);
            wm::store_matrix_sync(myscr, sc, 20, wm::mem_row_major);
            __syncwarp();
            if (lane < 16) {
                float v[16], mx = -1e30f;
#pragma unroll
                for (int m = 0; m < 16; m++) {
                    int bi = ((lane >> 2) - (m >> 2) + 3) * 7 + ((lane & 3) - (m & 3) + 3);
                    v[m] = myscr[lane * 20 + m] * SCALE + __ldg(btab + bi);
                    mx = fmaxf(mx, v[m]);
                }
                float s = 0.f;
#pragma unroll
                for (int m = 0; m < 16; m++) { v[m] = __expf(v[m] - mx); s += v[m]; }
                float inv = 1.0f / s;
                __half* pr = P + hh * 3072 + (warp * 16 + lane) * 24;
#pragma unroll
                for (int m = 0; m < 16; m++) pr[m] = __float2half(v[m] * inv);
            }
            __syncwarp();
        }

        // ---- V projection (overwrites KVH) ----
        {
            FC va[4];
#pragma unroll
            for (int f = 0; f < 4; f++) wm::fill_fragment(va[f], 0.0f);
            for (int kr = 0; kr < 2; kr++) {
                CPWAIT1(); __syncthreads();
                const __half* buf = DB[kr];
#pragma unroll
                for (int s2 = 0; s2 < 8; s2++) {
                    FA a2[2]; FBr b2[2];
#pragma unroll
                    for (int i = 0; i < 2; i++)
                        wm::load_matrix_sync(a2[i], ACT + (mrk * 32 + i * 16) * 264 + kr * 128 + s2 * 16, 264);
#pragma unroll
                    for (int i = 0; i < 2; i++)
                        wm::load_matrix_sync(b2[i], buf + (s2 * 16) * 72 + nck * 32 + i * 16, 72);
#pragma unroll
                    for (int fr = 0; fr < 2; fr++)
#pragma unroll
                        for (int fc = 0; fc < 2; fc++)
                            wm::mma_sync(va[fr * 2 + fc], a2[fr], b2[fc], va[fr * 2 + fc]);
                }
                __syncthreads();
                issue(nit, sb); nit++;
            }
#pragma unroll
            for (int f = 0; f < 4; f++) {
                int fr = f >> 1, fc = f & 1;
                wb16(va[f], myscr, KVH + (mrk * 32 + fr * 16) * 72 + nck * 32 + fc * 16, 72,
                     bkv, 256 + 64 * p + nck * 32 + fc * 16);
            }
        }
        __syncthreads();

        // ---- PV: per-window, OH[128][64+pad] ----
        for (int hh = 0; hh < 2; hh++) {
            FA pa;
            wm::load_matrix_sync(pa, P + hh * 3072 + (warp * 16) * 24, 24);
#pragma unroll
            for (int i = 0; i < 2; i++) {
                FBr bv;
                wm::load_matrix_sync(bv, KVH + (warp * 16) * 72 + hh * 32 + i * 16, 72);
                FC oh;
                wm::fill_fragment(oh, 0.0f);
                wm::mma_sync(oh, pa, bv, oh);
                wb16(oh, myscr, OH + (warp * 16) * 72 + hh * 32 + i * 16, 72, nullptr, 0);
            }
        }

        // ---- O accumulation: oacc += OH @ wo_pair ----
        CPWAIT0(); __syncthreads();
#pragma unroll
        for (int kk = 0; kk < 4; kk++) {
            const __half* buf = DB[kk >> 1];
            FA a4[4]; FBr b4[4];
#pragma unroll
            for (int i = 0; i < 4; i++)
                wm::load_matrix_sync(a4[i], OH + (mr * 64 + i * 16) * 72 + kk * 16, 72);
#pragma unroll
            for (int i = 0; i < 4; i++)
                wm::load_matrix_sync(b4[i], buf + ((kk & 1) * 16) * 264 + nc * 64 + i * 16, 264);
#pragma unroll
            for (int fr = 0; fr < 4; fr++)
#pragma unroll
                for (int fc = 0; fc < 4; fc++)
                    wm::mma_sync(oacc[fr * 4 + fc], a4[fr], b4[fc], oacc[fr * 4 + fc]);
        }
        __syncthreads();
        if (nit < 32) { issue(nit, sb); issue(nit + 1, sb); nit += 2; }
    }

    // ===== epilogue: oacc -> ep[128][260], wide token-major reads, coalesced gmem =====
    float* ep = (float*)sm;
#pragma unroll
    for (int f = 0; f < 16; f++) {
        int fr = f >> 2, fc = f & 3;
        wm::store_matrix_sync(ep + (size_t)(mr * 64 + fr * 16) * 260 + nc * 64 + fc * 16,
                              oacc[f], 260, wm::mem_row_major);
    }
    __syncthreads();
    {
        const int j = lane & 3, g = lane >> 2;
        for (int it = warp; it < 32; it += 8) {
            int c0 = (it >> 2) * 32, r = it & 3;
            int cbase = c0 + 8 * j;
            int t0 = g * 16 + r * 4;
            float vr[4][8];
#pragma unroll
            for (int k = 0; k < 4; k++) {
                *(float4*)&vr[k][0] = *(float4*)(ep + (size_t)(t0 + k) * 260 + cbase);
                *(float4*)&vr[k][4] = *(float4*)(ep + (size_t)(t0 + k) * 260 + cbase + 4);
            }
#pragma unroll
            for (int s = 0; s < 8; s++) {
                int c = cbase + s;
                size_t off = ((size_t)(b * 256 + c) * 384 + (h0 + r)) * 384 + w0 + 4 * g;
                float4 vx = *(const float4*)(x + off);
                float bias_o = __ldg(bo + c);
                float4 vo;
                vo.x = vx.x + vr[0][s] + bias_o;
                vo.y = vx.y + vr[1][s] + bias_o;
                vo.z = vx.z + vr[2][s] + bias_o;
                vo.w = vx.w + vr[3][s] + bias_o;
                *(float4*)(out + off) = vo;
            }
        }
    }
}

extern "C" void kernel_launch(void* const* d_in, const int* in_sizes, int n_in,
                              void* d_out, int out_size) {
    const float* x    = (const float*)d_in[0];
    const float* cond = (const float*)d_in[1];
    const float* n1w  = (const float*)d_in[2];
    const float* n2w  = (const float*)d_in[3];
    const float* wq   = (const float*)d_in[4];
    const float* bq   = (const float*)d_in[5];
    const float* wkv  = (const float*)d_in[6];
    const float* bkv  = (const float*)d_in[7];
    const float* wo   = (const float*)d_in[8];
    const float* bo   = (const float*)d_in[9];
    const float* btab = (const float*)d_in[10];
    float* out = (float*)d_out;

    int B = in_sizes[0] / (256 * 384 * 384);

    prep_kernel<<<1152, 256>>>(wq, wkv, wo);

    cudaFuncSetAttribute(xattn_kernel, cudaFuncAttributeMaxDynamicSharedMemorySize, SMEM_BYTES);
    dim3 grid(12, 96, B);
    xattn_kernel<<<grid, THREADS, SMEM_BYTES>>>(x, cond, n1w, n2w, bq, bkv, bo, btab, out);
}